// round 12
// baseline (speedup 1.0000x reference)
#include <cuda_runtime.h>
#include <cuda_fp16.h>
#include <cstdint>

// Problem constants
#define kR 8
#define kH 8
#define kDK 16
#define kD 128   // IN_DIM == OUT_DIM

// ---------------- scratch layout (single __device__ pool, float units) ----
#define OFF_Q     0ull
#define OFF_KH    6400000ull
#define OFF_VH    9600000ull
#define OFF_T     12800000ull
#define OFF_MSA   19200000ull
#define OFF_MSM   19210000ull
#define OFF_CNT   19220000ull
#define OFF_CUR   19630000ull
#define OFF_BSUM  20040000ull
#define OFF_SSRC  20050000ull
#define OFF_WP    21660000ull   // 4 x 8192 uint2 = 65536 floats
#define POOL_SZ   21800000ull

__device__ float g_pool[POOL_SZ];

// ---------------- tf32 helpers --------------------------------------------
__device__ __forceinline__ unsigned f2tf32(float f) {
    unsigned u;
    asm("cvt.rna.tf32.f32 %0, %1;" : "=r"(u) : "f"(f));
    return u;
}

__device__ __forceinline__ void mma_tf32(float* d, const unsigned* a, uint2 b) {
    asm volatile(
        "mma.sync.aligned.m16n8k8.row.col.f32.tf32.tf32.f32 "
        "{%0,%1,%2,%3}, {%4,%5,%6,%7}, {%8,%9}, {%0,%1,%2,%3};"
        : "+f"(d[0]), "+f"(d[1]), "+f"(d[2]), "+f"(d[3])
        : "r"(a[0]), "r"(a[1]), "r"(a[2]), "r"(a[3]), "r"(b.x), "r"(b.y));
}

// ---------------- pack W[128,128] into fragment-native tf32 layout --------
__global__ void pack_w(const float* __restrict__ W, uint2* __restrict__ Wp) {
    int i = blockIdx.x * blockDim.x + threadIdx.x;
    if (i >= 8192) return;
    int nt = i >> 9, ks = (i >> 5) & 15, lane = i & 31;
    int g = lane >> 2, t = lane & 3;
    int col = nt * 8 + g;
    int k = ks * 8 + t;
    uint2 o;
    o.x = f2tf32(W[col * 128 + k]);
    o.y = f2tf32(W[col * 128 + k + 4]);
    Wp[i] = o;
}

// ---------------- smem-staged tf32 GEMM helpers ----------------------------
#define AST 136
#define GEMM_SMEM (128 * AST * 4)

// single GEMM: fp32 out (optional fused skip) OR fp16 out
__global__ __launch_bounds__(256) void gemm_tf32(
    const float* __restrict__ A, const uint2* __restrict__ Wp,
    const float* __restrict__ bias, const float* __restrict__ S,
    const float* __restrict__ skipv, float* __restrict__ C,
    __half2* __restrict__ Ch, int n, int fuse)
{
    extern __shared__ float As[];
    int tid = threadIdx.x;
    int rbase = blockIdx.x * 128;

    for (int i = tid; i < 128 * 32; i += 256) {
        int row = i >> 5, c4 = i & 31;
        float4 v = make_float4(0.f, 0.f, 0.f, 0.f);
        if (rbase + row < n)
            v = *(const float4*)(A + (size_t)(rbase + row) * 128 + c4 * 4);
        *(float4*)(As + row * AST + c4 * 4) = v;
    }
    __syncthreads();

    int w = tid >> 5, lane = tid & 31;
    int g = lane >> 2, t = lane & 3;
    int rowA = w * 16 + g, rowB = rowA + 8;
    int rA = rbase + rowA, rB = rbase + rowB;
    bool okA = rA < n, okB = rB < n;
    const float* sA = As + rowA * AST + t;
    const float* sB = As + rowB * AST + t;

    float acc[16][4];
#pragma unroll
    for (int i = 0; i < 16; i++)
#pragma unroll
        for (int j = 0; j < 4; j++) acc[i][j] = 0.f;

#pragma unroll
    for (int ks = 0; ks < 16; ks++) {
        int k0 = ks * 8;
        unsigned a[4];
        a[0] = f2tf32(sA[k0]);
        a[1] = f2tf32(sB[k0]);
        a[2] = f2tf32(sA[k0 + 4]);
        a[3] = f2tf32(sB[k0 + 4]);
#pragma unroll
        for (int nt = 0; nt < 16; nt++) {
            uint2 b = Wp[(nt * 16 + ks) * 32 + lane];
            mma_tf32(acc[nt], a, b);
        }
    }

    float alpha = 1.f, beta = 0.f;
    if (fuse) {
        float sv = skipv[0];
        alpha = 1.f / (1.f + expf(-sv));
        beta = 1.f - alpha;
    }

#pragma unroll
    for (int nt = 0; nt < 16; nt++) {
        int col = nt * 8 + t * 2;
        float2 b2 = *(const float2*)(bias + col);
        float v0 = acc[nt][0] + b2.x;
        float v1 = acc[nt][1] + b2.y;
        float v2 = acc[nt][2] + b2.x;
        float v3 = acc[nt][3] + b2.y;
        if (Ch) {
            if (okA) Ch[(size_t)rA * 64 + (col >> 1)] = __floats2half2_rn(v0, v1);
            if (okB) Ch[(size_t)rB * 64 + (col >> 1)] = __floats2half2_rn(v2, v3);
        } else {
            if (okA) {
                if (fuse) {
                    float2 s2 = *(const float2*)(S + (size_t)rA * 128 + col);
                    v0 = alpha * v0 + beta * s2.x;
                    v1 = alpha * v1 + beta * s2.y;
                }
                *(float2*)(C + (size_t)rA * 128 + col) = make_float2(v0, v1);
            }
            if (okB) {
                if (fuse) {
                    float2 s2 = *(const float2*)(S + (size_t)rB * 128 + col);
                    v2 = alpha * v2 + beta * s2.x;
                    v3 = alpha * v3 + beta * s2.y;
                }
                *(float2*)(C + (size_t)rB * 128 + col) = make_float2(v2, v3);
            }
        }
    }
}

// dual GEMM: K and V projections from the same A tile (A read once)
__global__ __launch_bounds__(256) void gemm_kv(
    const float* __restrict__ A,
    const uint2* __restrict__ WpK, const uint2* __restrict__ WpV,
    const float* __restrict__ bk, const float* __restrict__ bv,
    __half2* __restrict__ kh, __half2* __restrict__ vh, int n)
{
    extern __shared__ float As[];
    int tid = threadIdx.x;
    int rbase = blockIdx.x * 128;

    for (int i = tid; i < 128 * 32; i += 256) {
        int row = i >> 5, c4 = i & 31;
        float4 v = make_float4(0.f, 0.f, 0.f, 0.f);
        if (rbase + row < n)
            v = *(const float4*)(A + (size_t)(rbase + row) * 128 + c4 * 4);
        *(float4*)(As + row * AST + c4 * 4) = v;
    }
    __syncthreads();

    int w = tid >> 5, lane = tid & 31;
    int g = lane >> 2, t = lane & 3;
    int rowA = w * 16 + g, rowB = rowA + 8;
    int rA = rbase + rowA, rB = rbase + rowB;
    bool okA = rA < n, okB = rB < n;
    const float* sA = As + rowA * AST + t;
    const float* sB = As + rowB * AST + t;

#pragma unroll
    for (int half = 0; half < 2; half++) {
        const uint2* Wp = half ? WpV : WpK;
        const float* bias = half ? bv : bk;
        __half2* Ch = half ? vh : kh;

        float acc[16][4];
#pragma unroll
        for (int i = 0; i < 16; i++)
#pragma unroll
            for (int j = 0; j < 4; j++) acc[i][j] = 0.f;

#pragma unroll
        for (int ks = 0; ks < 16; ks++) {
            int k0 = ks * 8;
            unsigned a[4];
            a[0] = f2tf32(sA[k0]);
            a[1] = f2tf32(sB[k0]);
            a[2] = f2tf32(sA[k0 + 4]);
            a[3] = f2tf32(sB[k0 + 4]);
#pragma unroll
            for (int nt = 0; nt < 16; nt++) {
                uint2 b = Wp[(nt * 16 + ks) * 32 + lane];
                mma_tf32(acc[nt], a, b);
            }
        }

#pragma unroll
        for (int nt = 0; nt < 16; nt++) {
            int col = nt * 8 + t * 2;
            float2 b2 = *(const float2*)(bias + col);
            if (okA) Ch[(size_t)rA * 64 + (col >> 1)] =
                __floats2half2_rn(acc[nt][0] + b2.x, acc[nt][1] + b2.y);
            if (okB) Ch[(size_t)rB * 64 + (col >> 1)] =
                __floats2half2_rn(acc[nt][2] + b2.x, acc[nt][3] + b2.y);
        }
    }
}

// ---------------- pack rel matrices into fp16 lane-major layout -----------
// Apply pattern in the edge kernel: out[j] = sum_i in[i] * P[r][h][i][j],
//   P stored at msp[r*2048 + i*128 + lane*4 + c], j = 4*(lane&3)+c, h=lane>>2.
// pack_msg: P = M        (out[e'] = sum_d va[d] M[d][e'])     -- message side
__global__ void pack_msg(const float* __restrict__ rmsg, __half* __restrict__ msp) {
    int r = blockIdx.x;
    for (int t = threadIdx.x; t < 2048; t += 256) {
        int d = t >> 7;
        int lane = (t >> 2) & 31;
        int i = t & 3;
        int h = lane >> 2;
        int ep = ((lane & 3) << 2) + i;
        float val = rmsg[((r * kH + h) * 16 + d) * 16 + ep];
        msp[r * 2048 + d * 128 + lane * 4 + i] = __float2half(val);
    }
}

// pack_att: P = A^T  (qrel[d] = sum_e q[e] A[d][e] = sum_e q[e] P[e][d])
//   -- attention side needs the TRANSPOSED pack (sum over A's second index)
__global__ void pack_att(const float* __restrict__ ratt, __half* __restrict__ msp) {
    int r = blockIdx.x;
    for (int t = threadIdx.x; t < 2048; t += 256) {
        int in = t >> 7;                 // summation index (= A's e)
        int lane = (t >> 2) & 31;
        int i = t & 3;
        int h = lane >> 2;
        int out = ((lane & 3) << 2) + i; // output index (= A's d)
        float val = ratt[((r * kH + h) * 16 + out) * 16 + in];
        msp[r * 2048 + in * 128 + lane * 4 + i] = __float2half(val);
    }
}

// ---------------- counting sort by seg = dst*8 + etype --------------------
__global__ void zero_cnt(unsigned* __restrict__ cnt, int nseg) {
    int i = blockIdx.x * blockDim.x + threadIdx.x;
    if (i <= nseg) cnt[i] = 0u;
}

__global__ void hist_kernel(const int* __restrict__ dst, const int* __restrict__ et,
                            unsigned* __restrict__ cnt, int e) {
    int i = blockIdx.x * blockDim.x + threadIdx.x;
    if (i < e) atomicAdd(&cnt[dst[i] * kR + et[i]], 1u);
}

__global__ __launch_bounds__(1024) void scan_local(
    const unsigned* __restrict__ cnt, unsigned* __restrict__ starts,
    unsigned* __restrict__ bsum, int nseg)
{
    __shared__ unsigned sm[1024];
    int tid = threadIdx.x;
    int g = blockIdx.x * 1024 + tid;
    unsigned x = (g < nseg) ? cnt[g] : 0u;
    sm[tid] = x; __syncthreads();
    for (int off = 1; off < 1024; off <<= 1) {
        unsigned val = sm[tid];
        if (tid >= off) val += sm[tid - off];
        __syncthreads(); sm[tid] = val; __syncthreads();
    }
    if (g < nseg) starts[g] = sm[tid] - x;
    if (tid == 1023) bsum[blockIdx.x] = sm[1023];
}

__global__ __launch_bounds__(1024) void scan_block(unsigned* __restrict__ bsum, int nb) {
    __shared__ unsigned sm[1024];
    int tid = threadIdx.x;
    unsigned x = (tid < nb) ? bsum[tid] : 0u;
    sm[tid] = x; __syncthreads();
    for (int off = 1; off < 1024; off <<= 1) {
        unsigned val = sm[tid];
        if (tid >= off) val += sm[tid - off];
        __syncthreads(); sm[tid] = val; __syncthreads();
    }
    if (tid < nb) bsum[tid] = sm[tid] - x;
}

__global__ void scan_add(unsigned* __restrict__ starts, unsigned* __restrict__ cur,
                         const unsigned* __restrict__ bsum, int nseg, int e) {
    int g = blockIdx.x * 1024 + threadIdx.x;
    if (g < nseg) {
        unsigned v = starts[g] + bsum[blockIdx.x];
        starts[g] = v;
        cur[g] = v;
    }
    if (g == 0) starts[nseg] = (unsigned)e;
}

__global__ void permute_kernel(const int* __restrict__ src, const int* __restrict__ dst,
                               const int* __restrict__ et, unsigned* __restrict__ cur,
                               int* __restrict__ ssrc, int e) {
    int i = blockIdx.x * blockDim.x + threadIdx.x;
    if (i >= e) return;
    int sg = dst[i] * kR + et[i];
    unsigned pos = atomicAdd(&cur[sg], 1u);
    ssrc[pos] = src[i];
}

// ---------------- fused edge pass v3 --------------------------------------
// inline A_r q (transposed-packed rel_att), L2-resident k/v gathers with
// 2-deep prefetch, per-segment softmax, per-segment M_r apply from smem.
__global__ __launch_bounds__(256) void fused_edge3(
    const unsigned* __restrict__ starts, const int* __restrict__ ssrc,
    const __half2* __restrict__ kh, const __half2* __restrict__ vh,
    const float* __restrict__ q,
    const __half* __restrict__ msAg, const __half* __restrict__ msMg,
    const float* __restrict__ rel_pri, float* __restrict__ t, int n)
{
    extern __shared__ __half sm2[];
    __half* smA = sm2;            // 16384 halves (32KB): packed rel_att^T
    __half* smM = sm2 + 16384;    // 16384 halves (32KB): packed rel_msg
    for (int i = threadIdx.x; i < 8192; i += 256) {
        ((uint32_t*)smA)[i] = ((const uint32_t*)msAg)[i];
        ((uint32_t*)smM)[i] = ((const uint32_t*)msMg)[i];
    }
    __syncthreads();

    int d = (int)(((size_t)blockIdx.x * blockDim.x + threadIdx.x) >> 5);
    int lane = threadIdx.x & 31;
    if (d >= n) return;
    int h = lane >> 2;

    float4 qv = ((const float4*)(q + (size_t)d * 128))[lane];
    float qc[4] = {qv.x, qv.y, qv.z, qv.w};

    float t4[4] = {0.f, 0.f, 0.f, 0.f};
    int nrel = 0;
    unsigned base = (unsigned)d * kR;

    for (int r = 0; r < kR; r++) {
        unsigned s0 = starts[base + r];
        unsigned s1 = starts[base + r + 1];
        if (s0 == s1) continue;
        nrel++;
        float pri = rel_pri[r * kH + h] * 0.25f;   // includes 1/sqrt(DK)

        // qrel_r[d'] = sum_e q[e] * A[d'][e]  via transposed pack
        float qr[4] = {0.f, 0.f, 0.f, 0.f};
#pragma unroll
        for (int dd = 0; dd < 16; dd++) {
            float vd = __shfl_sync(0xFFFFFFFFu, qc[dd & 3], (h << 2) | (dd >> 2));
            uint2 au = *(const uint2*)(smA + (((r * 16 + dd) * 32) + lane) * 4);
            float2 a01 = __half22float2(*(__half2*)&au.x);
            float2 a23 = __half22float2(*(__half2*)&au.y);
            qr[0] += vd * a01.x;
            qr[1] += vd * a01.y;
            qr[2] += vd * a23.x;
            qr[3] += vd * a23.y;
        }

        float ssum = 0.f;
        float acc[4] = {0.f, 0.f, 0.f, 0.f};

        // 2-deep prefetch gather loop
        uint2 kb[2], vb[2];
        {
            int sa = ssrc[s0];
            kb[0] = *(const uint2*)(kh + (size_t)sa * 64 + lane * 2);
            vb[0] = *(const uint2*)(vh + (size_t)sa * 64 + lane * 2);
            if (s0 + 1 < s1) {
                int sb = ssrc[s0 + 1];
                kb[1] = *(const uint2*)(kh + (size_t)sb * 64 + lane * 2);
                vb[1] = *(const uint2*)(vh + (size_t)sb * 64 + lane * 2);
            }
        }
        for (unsigned i = s0; i < s1; i++) {
            int slot = (int)((i - s0) & 1u);
            uint2 ck = kb[slot], cv = vb[slot];
            if (i + 2 < s1) {
                int ns = ssrc[i + 2];
                kb[slot] = *(const uint2*)(kh + (size_t)ns * 64 + lane * 2);
                vb[slot] = *(const uint2*)(vh + (size_t)ns * 64 + lane * 2);
            }
            float2 k01 = __half22float2(*(__half2*)&ck.x);
            float2 k23 = __half22float2(*(__half2*)&ck.y);
            float p = k01.x * qr[0] + k01.y * qr[1] + k23.x * qr[2] + k23.y * qr[3];
            p += __shfl_xor_sync(0xFFFFFFFFu, p, 1);
            p += __shfl_xor_sync(0xFFFFFFFFu, p, 2);
            float w = __expf(p * pri);
            float2 v01 = __half22float2(*(__half2*)&cv.x);
            float2 v23 = __half22float2(*(__half2*)&cv.y);
            ssum += w;
            acc[0] += w * v01.x;
            acc[1] += w * v01.y;
            acc[2] += w * v23.x;
            acc[3] += w * v23.y;
        }
        float inv = 1.f / ssum;
        float va[4] = {acc[0] * inv, acc[1] * inv, acc[2] * inv, acc[3] * inv};

        // apply M_r: t_e' += sum_d va[d] * M[d][e']  (per head)
#pragma unroll
        for (int dd = 0; dd < 16; dd++) {
            float vd = __shfl_sync(0xFFFFFFFFu, va[dd & 3], (h << 2) | (dd >> 2));
            uint2 mu = *(const uint2*)(smM + (((r * 16 + dd) * 32) + lane) * 4);
            float2 m01 = __half22float2(*(__half2*)&mu.x);
            float2 m23 = __half22float2(*(__half2*)&mu.y);
            t4[0] += vd * m01.x;
            t4[1] += vd * m01.y;
            t4[2] += vd * m23.x;
            t4[3] += vd * m23.y;
        }
    }
    float ninv = 1.f / (float)max(nrel, 1);
    ((float4*)(t + (size_t)d * 128))[lane] =
        make_float4(t4[0] * ninv, t4[1] * ninv, t4[2] * ninv, t4[3] * ninv);
}

// ---------------- launch ---------------------------------------------------
extern "C" void kernel_launch(void* const* d_in, const int* in_sizes, int n_in,
                              void* d_out, int out_size) {
    const float* src_h   = (const float*)d_in[0];
    const float* dst_h   = (const float*)d_in[1];
    const float* Wk      = (const float*)d_in[2];
    const float* bk      = (const float*)d_in[3];
    const float* Wq      = (const float*)d_in[4];
    const float* bq      = (const float*)d_in[5];
    const float* Wv      = (const float*)d_in[6];
    const float* bv      = (const float*)d_in[7];
    const float* Wa      = (const float*)d_in[8];
    const float* ba      = (const float*)d_in[9];
    const float* rel_pri = (const float*)d_in[10];
    const float* rel_att = (const float*)d_in[11];
    const float* rel_msg = (const float*)d_in[12];
    const float* skip    = (const float*)d_in[13];
    const int* src_idx   = (const int*)d_in[14];
    const int* dst_idx   = (const int*)d_in[15];
    const int* etype     = (const int*)d_in[16];
    float* out = (float*)d_out;

    int n = in_sizes[0] / kD;
    int e = in_sizes[14];
    int nseg = n * kR;

    static bool inited = false;
    static cudaStream_t s1, s2, s3;
    static cudaEvent_t evRoot, ev1, ev2, ev3;
    if (!inited) {
        cudaStreamCreateWithFlags(&s1, cudaStreamNonBlocking);
        cudaStreamCreateWithFlags(&s2, cudaStreamNonBlocking);
        cudaStreamCreateWithFlags(&s3, cudaStreamNonBlocking);
        cudaEventCreateWithFlags(&evRoot, cudaEventDisableTiming);
        cudaEventCreateWithFlags(&ev1, cudaEventDisableTiming);
        cudaEventCreateWithFlags(&ev2, cudaEventDisableTiming);
        cudaEventCreateWithFlags(&ev3, cudaEventDisableTiming);
        cudaFuncSetAttribute(gemm_tf32, cudaFuncAttributeMaxDynamicSharedMemorySize,
                             GEMM_SMEM);
        cudaFuncSetAttribute(gemm_kv, cudaFuncAttributeMaxDynamicSharedMemorySize,
                             GEMM_SMEM);
        cudaFuncSetAttribute(fused_edge3, cudaFuncAttributeMaxDynamicSharedMemorySize,
                             65536);
        inited = true;
    }

    float* pool = nullptr;
    cudaGetSymbolAddress((void**)&pool, g_pool);
    float* pq      = pool + OFF_Q;
    __half2* pkh   = (__half2*)(pool + OFF_KH);
    __half2* pvh   = (__half2*)(pool + OFF_VH);
    float* pt      = pool + OFF_T;
    __half* pmsA   = (__half*)(pool + OFF_MSA);
    __half* pmsM   = (__half*)(pool + OFF_MSM);
    unsigned* pcnt  = (unsigned*)(pool + OFF_CNT);
    unsigned* pcur  = (unsigned*)(pool + OFF_CUR);
    unsigned* pbsum = (unsigned*)(pool + OFF_BSUM);
    int* pssrc      = (int*)(pool + OFF_SSRC);
    uint2* pWq = (uint2*)(pool + OFF_WP);
    uint2* pWk = pWq + 8192;
    uint2* pWv = pWq + 16384;
    uint2* pWa = pWq + 24576;

    int gemm_blocks = (n + 127) / 128;
    int nb = (nseg + 1023) / 1024;

    cudaEventRecord(evRoot, 0);
    cudaStreamWaitEvent(s1, evRoot, 0);
    cudaStreamWaitEvent(s2, evRoot, 0);
    cudaStreamWaitEvent(s3, evRoot, 0);

    // s1: counting sort + rel matrix packs
    zero_cnt<<<(nseg + 256) / 256, 256, 0, s1>>>(pcnt, nseg);
    hist_kernel<<<(e + 255) / 256, 256, 0, s1>>>(dst_idx, etype, pcnt, e);
    scan_local<<<nb, 1024, 0, s1>>>(pcnt, pcnt, pbsum, nseg);
    scan_block<<<1, 1024, 0, s1>>>(pbsum, nb);
    scan_add<<<nb, 1024, 0, s1>>>(pcnt, pcur, pbsum, nseg, e);
    permute_kernel<<<(e + 255) / 256, 256, 0, s1>>>(src_idx, dst_idx, etype, pcur, pssrc, e);
    pack_att<<<kR, 256, 0, s1>>>(rel_att, pmsA);   // TRANSPOSED pack (bug fix)
    pack_msg<<<kR, 256, 0, s1>>>(rel_msg, pmsM);
    cudaEventRecord(ev1, s1);

    // s2: K+V merged projection
    pack_w<<<32, 256, 0, s2>>>(Wk, pWk);
    pack_w<<<32, 256, 0, s2>>>(Wv, pWv);
    gemm_kv<<<gemm_blocks, 256, GEMM_SMEM, s2>>>(src_h, pWk, pWv, bk, bv, pkh, pvh, n);
    cudaEventRecord(ev2, s2);

    // s3: Wa pack (needed only by the final GEMM)
    pack_w<<<32, 256, 0, s3>>>(Wa, pWa);
    cudaEventRecord(ev3, s3);

    // main: Q projection (fp32 out)
    pack_w<<<32, 256>>>(Wq, pWq);
    gemm_tf32<<<gemm_blocks, 256, GEMM_SMEM>>>(dst_h, pWq, bq, nullptr, nullptr,
                                               pq, nullptr, n, 0);

    // join sort + KV before the fused edge pass
    cudaStreamWaitEvent(0, ev1, 0);
    cudaStreamWaitEvent(0, ev2, 0);

    fused_edge3<<<((size_t)n * 32 + 255) / 256, 256, 65536>>>(
        pcnt, pssrc, pkh, pvh, pq, pmsA, pmsM, rel_pri, pt, n);

    // join Wa pack, then output projection + skip
    cudaStreamWaitEvent(0, ev3, 0);
    gemm_tf32<<<gemm_blocks, 256, GEMM_SMEM>>>(pt, pWa, ba, dst_h, skip, out,
                                               nullptr, n, 1);
}